// round 16
// baseline (speedup 1.0000x reference)
#include <cuda_runtime.h>
#include <cuda_fp16.h>
#include <math.h>
#include <stdint.h>

// ===========================================================================
// DRConv via warp-level fp16 tensor cores (mma.sync.m16n8k16, plain sm_103):
//   out[b,o,p] = bias[o] + sum_t c[b,t,p] * (W_t (*) x)[b,o,p]
// R16 = R14 with the prep grid fixed (weight branch needs 4608 blocks; R15
// launched 18, leaving g_Wh ~all zeros -> rel_err ~1.0).
// 512-thread conv CTA (16 warps, 4m x 4n; warp tile 32oc x 32px); 36 full-K
// stages; 3-buffer A cp.async pipeline; both 64-ci B slabs resident;
// 4 templates fused with in-register c_t fold. Single-term fp16, fp32 accum.
// ===========================================================================

#define B_    8
#define C_    128
#define O_    128
#define H_    56
#define W_    56
#define HW_   3136
#define G_    8
#define T_    8
#define PW_   58
#define PQ_   (PW_*PW_)
#define QPAD_ 3456             // 27*128
#define PROW_ 3712             // 64 guard + 3364 + guard

// ---------------- device scratch (static) ----------------
__device__ __align__(128) __half g_Ph[B_*PROW_*C_];     // padded fp16 input
__device__ __align__(128) __half g_Wh[T_*9*O_*C_];      // fp16 weights
__device__ float g_xse[B_*64];
__device__ float g_cq[B_*T_*QPAD_];
__device__ float g_p2[2*B_*O_*QPAD_];                   // half-partials

// ---------------- PTX helpers ----------------
__device__ __forceinline__ uint32_t smem_u32(const void* p) {
    uint32_t a;
    asm("{ .reg .u64 t; cvta.to.shared.u64 t, %1; cvt.u32.u64 %0, t; }" : "=r"(a) : "l"(p));
    return a;
}
__device__ __forceinline__ void ldm4(uint32_t r[4], uint32_t addr) {
    asm volatile("ldmatrix.sync.aligned.m8n8.x4.shared.b16 {%0,%1,%2,%3}, [%4];"
        : "=r"(r[0]), "=r"(r[1]), "=r"(r[2]), "=r"(r[3]) : "r"(addr));
}
__device__ __forceinline__ void mma16816(float d[4], const uint32_t a[4],
                                         uint32_t b0, uint32_t b1) {
    asm volatile("mma.sync.aligned.m16n8k16.row.col.f32.f16.f16.f32 "
        "{%0,%1,%2,%3}, {%4,%5,%6,%7}, {%8,%9}, {%0,%1,%2,%3};"
        : "+f"(d[0]), "+f"(d[1]), "+f"(d[2]), "+f"(d[3])
        : "r"(a[0]), "r"(a[1]), "r"(a[2]), "r"(a[3]), "r"(b0), "r"(b1));
}
__device__ __forceinline__ void cpasync16(uint32_t saddr, const void* g) {
    asm volatile("cp.async.cg.shared.global [%0], [%1], 16;" :: "r"(saddr), "l"(g));
}
#define CP_COMMIT() asm volatile("cp.async.commit_group;" ::: "memory")

// ---------------------------------------------------------------------------
// Fused prep: blocks [0,448) pad+convert input; blocks [448,448+4608) weights.
// ---------------------------------------------------------------------------
#define WBLK_ ((T_*9*O_*C_ + 255) / 256)   // 4608
__global__ void prep_kernel(const float* __restrict__ inputs,
                            const float* __restrict__ wt) {
    int bx = blockIdx.x, tid = threadIdx.x;
    if (bx < 448) {
        __shared__ float tile[128 * 57];
        int h = bx % 56, b = bx / 56;
        for (int idx = tid; idx < 128 * 56; idx += 256) {
            int ci = idx / 56, w = idx % 56;
            tile[ci * 57 + w] = inputs[(((size_t)b * C_ + ci) * H_ + h) * W_ + w];
        }
        __syncthreads();
        for (int idx = tid; idx < 56 * 128; idx += 256) {
            int w = idx >> 7, ci = idx & 127;
            size_t row = (size_t)b * PROW_ + 64 + (h + 1) * PW_ + (w + 1);
            g_Ph[row * C_ + ci] = __float2half(tile[ci * 57 + w]);
        }
    } else {
        int idx = (bx - 448) * 256 + tid;
        if (idx >= T_ * 9 * O_ * C_) return;
        int ci = idx & 127;
        int o  = (idx >> 7) & 127;
        int tt = idx >> 14;
        int t = tt / 9, tap = tt % 9;
        g_Wh[idx] = __float2half(wt[((size_t)o * 1152 + ci * 9 + tap) * 8 + t]);
    }
}

// ---------------------------------------------------------------------------
// Fused routing: GAP (1 warp/channel) + fc + scaled sigmoid. grid=B, 1024 thr
// ---------------------------------------------------------------------------
__global__ void gapxse_kernel(const float* __restrict__ inputs,
                              const float* __restrict__ routing_w,
                              const float* __restrict__ routing_b) {
    __shared__ float sg[128];
    int b = blockIdx.x, tid = threadIdx.x;
    int lane = tid & 31, wid = tid >> 5;
    for (int c = wid; c < C_; c += 32) {
        const float* p = inputs + ((size_t)b * C_ + c) * HW_;
        float s = 0.f;
        for (int i = lane; i < HW_; i += 32) s += p[i];
        #pragma unroll
        for (int off = 16; off > 0; off >>= 1)
            s += __shfl_down_sync(0xffffffffu, s, off);
        if (lane == 0) sg[c] = s / (float)HW_;
    }
    __syncthreads();
    if (tid < 256) {
        int j = tid >> 2, sl = tid & 3;
        float s = 0.f;
        #pragma unroll 8
        for (int c = sl; c < C_; c += 4) s += sg[c] * routing_w[j * C_ + c];
        s += __shfl_xor_sync(0xffffffffu, s, 1);
        s += __shfl_xor_sync(0xffffffffu, s, 2);
        if (sl == 0) g_xse[b * 64 + j] = 0.25f / (1.f + expf(-(s + routing_b[j])));
    }
}

// ---------------------------------------------------------------------------
// Per-pixel coefficients on padded q grid (0 on borders)
// ---------------------------------------------------------------------------
__global__ void coeff_kernel(const float* __restrict__ Alpha,
                             const int* __restrict__ mask,
                             const void* __restrict__ use_alpha_ptr) {
    int b = blockIdx.y;
    int q = blockIdx.x * 128 + threadIdx.x;
    __shared__ float sx[64];
    if (threadIdx.x < 64) sx[threadIdx.x] = g_xse[b * 64 + threadIdx.x];
    __syncthreads();
    if (q >= QPAD_) return;
    int h = q / PW_ - 1, w = q % PW_ - 1;
    bool valid = (h >= 0 && h < H_ && w >= 0 && w < W_ && q < PQ_);
    if (!valid) {
        #pragma unroll
        for (int t = 0; t < T_; t++) g_cq[((size_t)b * T_ + t) * QPAD_ + q] = 0.f;
        return;
    }
    int p = h * W_ + w;
    bool ua = true;
    if (use_alpha_ptr) ua = (*(const int*)use_alpha_ptr) != 0;
    float pr[G_];
    if (ua) {
        float a[G_], m = -1e30f;
        #pragma unroll
        for (int g = 0; g < G_; g++) {
            a[g] = Alpha[((size_t)b * G_ + g) * HW_ + p];
            m = fmaxf(m, a[g]);
        }
        float sum = 0.f;
        #pragma unroll
        for (int g = 0; g < G_; g++) { pr[g] = expf(a[g] - m); sum += pr[g]; }
        float inv = 1.f / sum;
        #pragma unroll
        for (int g = 0; g < G_; g++) pr[g] *= inv;
    } else {
        int mk = mask[(size_t)b * HW_ + p];
        #pragma unroll
        for (int g = 0; g < G_; g++) pr[g] = (g == mk) ? 1.f : 0.f;
    }
    #pragma unroll
    for (int t = 0; t < T_; t++) {
        float s = 0.f;
        #pragma unroll
        for (int g = 0; g < G_; g++) s += pr[g] * sx[g * 8 + t];
        g_cq[((size_t)b * T_ + t) * QPAD_ + q] = s;
    }
}

// ---------------------------------------------------------------------------
// Conv. Grid (27, 2, 8) = (qg, template-half, b); 512 thr, 16 warps (4m x 4n).
// Warp tile 32oc x 32px. 36 stages (template, tap), full K=128/stage.
// A tiles in 3-buffer cp.async rotation; both 64-ci B slabs resident.
// Fold acc += c_t * d at tap==8 (exact by linearity).
// ---------------------------------------------------------------------------
#define BSTR_   144
#define NROW_   246
#define SLABSZ_ (NROW_ * BSTR_)           // 35424
#define ASTR_   272
#define ASZ_    (128 * ASTR_)             // 34816
#define A_OFF_  (2 * SLABSZ_)             // 70848
#define CS_OFF_ (A_OFF_ + 3 * ASZ_)       // 175296
#define SMEM2_  (CS_OFF_ + 4 * 128 * 4)   // 177344

__global__ __launch_bounds__(512, 1) void conv_mma_kernel() {
    extern __shared__ char sb[];
    const uint32_t s0 = smem_u32(sb);
    const int tid  = threadIdx.x;
    const int lane = tid & 31, wid = tid >> 5;
    const int wm = wid >> 2, wn = wid & 3;        // 4 x 4 warp grid
    const int q0   = blockIdx.x * 128;
    const int half = blockIdx.y;
    const int b    = blockIdx.z;
    const int t0   = half * 4;

    float* cs = (float*)(sb + CS_OFF_);
    {
        int tt = tid >> 7, px = tid & 127;
        cs[tid] = g_cq[((size_t)b * T_ + t0 + tt) * QPAD_ + q0 + px];
    }

    const size_t prow0 = (size_t)b * PROW_ + 64 + q0;
    const int lr = (lane & 7) + ((lane >> 3) & 1) * 8;
    const int kg = lane >> 4;

    float acc[2][4][4];
    float d[2][4][4];
    #pragma unroll
    for (int i = 0; i < 2; i++)
        #pragma unroll
        for (int j = 0; j < 4; j++)
            #pragma unroll
            for (int k = 0; k < 4; k++) { acc[i][j][k] = 0.f; d[i][j][k] = 0.f; }

    auto issueA = [&](int s) {
        int tt = s / 9, tap = s - tt * 9;
        const __half* gA = g_Wh + ((size_t)(t0 + tt) * 9 + tap) * (128 * 128);
        uint32_t dst = s0 + A_OFF_ + (s % 3) * ASZ_;
        #pragma unroll
        for (int it = 0; it < 4; it++) {
            int idx = it * 512 + tid;
            int row = idx >> 4, q = idx & 15;
            cpasync16(dst + row * ASTR_ + q * 16, gA + (size_t)row * 128 + q * 8);
        }
    };
    auto issueB = [&](int c) {
        const size_t gRow0 = prow0 - 59;
        uint32_t dst = s0 + c * SLABSZ_;
        for (int idx = tid; idx < NROW_ * 8; idx += 512) {
            int row = idx >> 3, q = idx & 7;
            cpasync16(dst + row * BSTR_ + q * 16,
                      g_Ph + (gRow0 + row) * 128 + c * 64 + q * 8);
        }
    };

    issueB(0); issueB(1); issueA(0); CP_COMMIT();   // group 0
    issueA(1); CP_COMMIT();                          // group 1

    #pragma unroll 1
    for (int s = 0; s < 36; s++) {
        if (s < 34) asm volatile("cp.async.wait_group 1;" ::: "memory");
        else        asm volatile("cp.async.wait_group 0;" ::: "memory");
        __syncthreads();
        if (s + 2 < 36) { issueA(s + 2); CP_COMMIT(); }

        const int tap = s % 9;
        const uint32_t abase = s0 + A_OFF_ + (s % 3) * ASZ_;
        const int d59 = (tap / 3) * PW_ + (tap % 3);

        #pragma unroll
        for (int ks = 0; ks < 8; ks++) {
            const uint32_t akoff = ks * 32 + kg * 16;
            const uint32_t bbase = s0 + (ks >> 2) * SLABSZ_;
            const uint32_t bkoff = (ks & 3) * 32 + kg * 16;
            uint32_t a0[4], a1[4];
            ldm4(a0, abase + (wm * 32 + 0  + lr) * ASTR_ + akoff);
            ldm4(a1, abase + (wm * 32 + 16 + lr) * ASTR_ + akoff);
            #pragma unroll
            for (int pr = 0; pr < 2; pr++) {
                const int rowb = wn * 32 + pr * 16 + lr + d59;
                uint32_t bh[4];
                ldm4(bh, bbase + rowb * BSTR_ + bkoff);
                mma16816(d[0][2*pr],   a0, bh[0], bh[2]);
                mma16816(d[0][2*pr+1], a0, bh[1], bh[3]);
                mma16816(d[1][2*pr],   a1, bh[0], bh[2]);
                mma16816(d[1][2*pr+1], a1, bh[1], bh[3]);
            }
        }

        if (tap == 8) {   // template finished: fold with c_t
            const float* cst = cs + (s / 9) * 128;
            #pragma unroll
            for (int nt = 0; nt < 4; nt++) {
                const int px = wn * 32 + nt * 8 + 2 * (lane & 3);
                const float c0v = cst[px], c1v = cst[px + 1];
                #pragma unroll
                for (int mt = 0; mt < 2; mt++) {
                    acc[mt][nt][0] += d[mt][nt][0] * c0v;
                    acc[mt][nt][1] += d[mt][nt][1] * c1v;
                    acc[mt][nt][2] += d[mt][nt][2] * c0v;
                    acc[mt][nt][3] += d[mt][nt][3] * c1v;
                    d[mt][nt][0] = 0.f; d[mt][nt][1] = 0.f;
                    d[mt][nt][2] = 0.f; d[mt][nt][3] = 0.f;
                }
            }
        }
    }

    // epilogue: write half-partials
    float* pbase = g_p2 + (((size_t)half * B_ + b) * O_) * QPAD_;
    const int r0 = lane >> 2;
    const int c0 = 2 * (lane & 3);
    #pragma unroll
    for (int mt = 0; mt < 2; mt++) {
        int oc = wm * 32 + mt * 16 + r0;
        #pragma unroll
        for (int nt = 0; nt < 4; nt++) {
            int px = wn * 32 + nt * 8 + c0;
            *(float2*)(pbase + (size_t)oc * QPAD_ + q0 + px) =
                make_float2(acc[mt][nt][0], acc[mt][nt][1]);
            *(float2*)(pbase + (size_t)(oc + 8) * QPAD_ + q0 + px) =
                make_float2(acc[mt][nt][2], acc[mt][nt][3]);
        }
    }
}

// ---------------------------------------------------------------------------
// Combine: out = bias + half0 + half1
// ---------------------------------------------------------------------------
__global__ void combine_kernel(const float* __restrict__ bias,
                               float* __restrict__ out) {
    size_t idx = (size_t)blockIdx.x * 256 + threadIdx.x;
    int p   = (int)(idx % HW_);
    int rem = (int)(idx / HW_);
    int o   = rem & 127;
    int b   = rem >> 7;
    int h = p / W_, w = p % W_;
    int q = (h + 1) * PW_ + (w + 1);
    size_t base = (((size_t)b) * O_ + o) * QPAD_ + q;
    out[idx] = bias[o] + g_p2[base] + g_p2[(size_t)B_ * O_ * QPAD_ + base];
}

// ---------------------------------------------------------------------------
extern "C" void kernel_launch(void* const* d_in, const int* in_sizes, int n_in,
                              void* d_out, int out_size) {
    const float* inputs     = (const float*)d_in[0];
    const int*   mask       = (const int*)  d_in[1];
    const float* Alpha      = (const float*)d_in[2];
    const float* wt         = (const float*)d_in[3];
    const float* routing_w  = (const float*)d_in[4];
    const float* routing_b  = (const float*)d_in[5];
    const float* bias       = (const float*)d_in[6];
    const void*  use_alpha  = (n_in > 7) ? d_in[7] : nullptr;
    float* out = (float*)d_out;

    cudaFuncSetAttribute(conv_mma_kernel,
                         cudaFuncAttributeMaxDynamicSharedMemorySize, SMEM2_);

    prep_kernel<<<448 + WBLK_, 256>>>(inputs, wt);
    gapxse_kernel<<<B_, 1024>>>(inputs, routing_w, routing_b);
    coeff_kernel<<<dim3(QPAD_ / 128, B_), 128>>>(Alpha, mask, use_alpha);
    conv_mma_kernel<<<dim3(QPAD_ / 128, 2, B_), 512, SMEM2_>>>();
    combine_kernel<<<(B_ * O_ * HW_) / 256, 256>>>(bias, out);
}